// round 7
// baseline (speedup 1.0000x reference)
#include <cuda_runtime.h>
#include <cuda_fp16.h>
#include <stdint.h>
#include <math.h>

#define MTOT 16384
#define CDIM 512
#define NQKV 1536

// ---------------------------------------------------------------------------
// Scratch (static __device__: no allocations allowed)
// ---------------------------------------------------------------------------
__device__ __half g_x16[MTOT * CDIM];
__device__ __half g_qkv16[(size_t)MTOT * NQKV];
__device__ __half g_s16[MTOT * CDIM];
__device__ __half g_w16[4 * CDIM * CDIM];   // Wq, Wk, Wv, proj

// ---------------------------------------------------------------------------
// PTX helpers (arch-portable)
// ---------------------------------------------------------------------------
__device__ __forceinline__ uint32_t smem_u32(const void* p) {
    uint32_t a;
    asm("{ .reg .u64 t; cvta.to.shared.u64 t, %1; cvt.u32.u64 %0, t; }"
        : "=r"(a) : "l"(p));
    return a;
}
__device__ __forceinline__ void ldm_x4(uint32_t* r, uint32_t addr) {
    asm volatile("ldmatrix.sync.aligned.m8n8.x4.shared.b16 {%0,%1,%2,%3}, [%4];"
                 : "=r"(r[0]), "=r"(r[1]), "=r"(r[2]), "=r"(r[3]) : "r"(addr));
}
__device__ __forceinline__ void mma_f16(float* d, const uint32_t* a, const uint32_t* b) {
    asm volatile(
        "mma.sync.aligned.m16n8k16.row.col.f32.f16.f16.f32 "
        "{%0,%1,%2,%3}, {%4,%5,%6,%7}, {%8,%9}, {%0,%1,%2,%3};"
        : "+f"(d[0]), "+f"(d[1]), "+f"(d[2]), "+f"(d[3])
        : "r"(a[0]), "r"(a[1]), "r"(a[2]), "r"(a[3]), "r"(b[0]), "r"(b[1]));
}
__device__ __forceinline__ void cp_async16(uint32_t dst, const void* src) {
    asm volatile("cp.async.cg.shared.global [%0], [%1], 16;" :: "r"(dst), "l"(src));
}
#define CP_COMMIT() asm volatile("cp.async.commit_group;" ::: "memory")
#define CP_WAIT(N)  asm volatile("cp.async.wait_group %0;" :: "n"(N) : "memory")

// ---------------------------------------------------------------------------
// fp16 GEMM: C[m,n] = sum_k A[m,k] * B[n,k] (+bias)
// BM=128, BN=256, BK=32, 256 threads, 8 warps (2x4), warp tile 64x64:
// 32 MMAs per 8 ldmatrix per k16 step. 4-stage cp.async pipeline.
// ---------------------------------------------------------------------------
#define PITCH 40
#define SH ((128 + 256) * PITCH)
#define OFF_B (128 * PITCH)
#define GSMEM (4 * SH * 2)                  // 122880 B

template <bool HOUT>
__global__ __launch_bounds__(256, 1)
void gemm_f16(const __half* __restrict__ A, const __half* __restrict__ B,
              const float* __restrict__ bias, void* __restrict__ Cv, int ldc)
{
    extern __shared__ __align__(16) __half sm[];
    const int tid = threadIdx.x;
    const int wid = tid >> 5, L = tid & 31;
    const int m0 = blockIdx.y * 128;
    const int n0 = blockIdx.x * 256;
    const int wm = (wid >> 2) * 64;
    const int wn = (wid & 3) * 64;
    const uint32_t sb = smem_u32(sm);

    const __half* Ab = A + (size_t)m0 * CDIM;
    const __half* Bb = B + (size_t)n0 * CDIM;

    float acc[4][8][4];
#pragma unroll
    for (int i = 0; i < 4; i++)
#pragma unroll
        for (int j = 0; j < 8; j++)
#pragma unroll
            for (int q = 0; q < 4; q++) acc[i][j][q] = 0.f;

    const int aRow = L & 15, aK = (L >> 4) * 8;
    const int bRowL = (L & 7) + ((L & 16) ? 8 : 0);
    const int bK = ((L >> 3) & 1) * 8;

    auto load_stage = [&](int stage, int k0) {
        const uint32_t s0 = sb + (uint32_t)stage * SH * 2;
        // A: 128 rows x 4 chunks = 512 cp; 2 per thread
#pragma unroll
        for (int j = 0; j < 2; j++) {
            int idx = tid + j * 256;
            int r = idx >> 2, c = idx & 3;
            cp_async16(s0 + (uint32_t)(r * PITCH + c * 8) * 2,
                       Ab + (size_t)r * CDIM + k0 + c * 8);
        }
        // B: 256 rows x 4 chunks = 1024 cp; 4 per thread
#pragma unroll
        for (int j = 0; j < 4; j++) {
            int idx = tid + j * 256;
            int r = idx >> 2, c = idx & 3;
            cp_async16(s0 + OFF_B * 2 + (uint32_t)(r * PITCH + c * 8) * 2,
                       Bb + (size_t)r * CDIM + k0 + c * 8);
        }
    };

    load_stage(0, 0);  CP_COMMIT();
    load_stage(1, 32); CP_COMMIT();
    load_stage(2, 64); CP_COMMIT();

    const int NIT = CDIM / 32;
    for (int s = 0; s < NIT; s++) {
        CP_WAIT(2);
        __syncthreads();
        if (s + 3 < NIT) load_stage((s + 3) & 3, (s + 3) * 32);
        CP_COMMIT();

        const uint32_t pA = sb + (uint32_t)(s & 3) * SH * 2;
        const uint32_t pB = pA + OFF_B * 2;

#pragma unroll
        for (int kk = 0; kk < 32; kk += 16) {
            uint32_t ah[4][4], bh[8][2];
#pragma unroll
            for (int mi = 0; mi < 4; mi++) {
                uint32_t ro = (uint32_t)((wm + mi * 16 + aRow) * PITCH + kk + aK) * 2;
                ldm_x4(ah[mi], pA + ro);
            }
#pragma unroll
            for (int nb = 0; nb < 4; nb++) {
                uint32_t ro = (uint32_t)((wn + nb * 16 + bRowL) * PITCH + kk + bK) * 2;
                uint32_t th[4];
                ldm_x4(th, pB + ro);
                bh[nb * 2][0] = th[0];     bh[nb * 2][1] = th[1];
                bh[nb * 2 + 1][0] = th[2]; bh[nb * 2 + 1][1] = th[3];
            }
#pragma unroll
            for (int mi = 0; mi < 4; mi++)
#pragma unroll
                for (int ni = 0; ni < 8; ni++)
                    mma_f16(acc[mi][ni], ah[mi], bh[ni]);
        }
        __syncthreads();
    }

    const int cr = L >> 2, cc = (L & 3) * 2;
#pragma unroll
    for (int mi = 0; mi < 4; mi++) {
#pragma unroll
        for (int ni = 0; ni < 8; ni++) {
            int row = m0 + wm + mi * 16 + cr;
            int col = n0 + wn + ni * 8 + cc;
            float b0 = 0.f, b1 = 0.f;
            if (bias) { b0 = bias[col]; b1 = bias[col + 1]; }
            if (HOUT) {
                __half* C = (__half*)Cv;
                *(__half2*)&C[(size_t)row * ldc + col] =
                    __floats2half2_rn(acc[mi][ni][0] + b0, acc[mi][ni][1] + b1);
                *(__half2*)&C[(size_t)(row + 8) * ldc + col] =
                    __floats2half2_rn(acc[mi][ni][2] + b0, acc[mi][ni][3] + b1);
            } else {
                float* C = (float*)Cv;
                *(float2*)&C[(size_t)row * ldc + col] =
                    make_float2(acc[mi][ni][0] + b0, acc[mi][ni][1] + b1);
                *(float2*)&C[(size_t)(row + 8) * ldc + col] =
                    make_float2(acc[mi][ni][2] + b0, acc[mi][ni][3] + b1);
            }
        }
    }
}

// ---------------------------------------------------------------------------
// fp32 -> fp16 converts
// ---------------------------------------------------------------------------
__global__ void cvt_x(const float4* __restrict__ src, uint2* __restrict__ dst, int n4)
{
    int i = blockIdx.x * blockDim.x + threadIdx.x;
    if (i >= n4) return;
    float4 v = src[i];
    union { uint2 u; __half b[4]; } H;
    H.b[0] = __float2half(v.x); H.b[1] = __float2half(v.y);
    H.b[2] = __float2half(v.z); H.b[3] = __float2half(v.w);
    dst[i] = H.u;
}

__global__ void cvt_w(const float4* __restrict__ w0, const float4* __restrict__ w1,
                      const float4* __restrict__ w2, const float4* __restrict__ w3,
                      uint2* __restrict__ dst)
{
    int wsel = blockIdx.y;
    const float4* src = (wsel == 0) ? w0 : (wsel == 1) ? w1 : (wsel == 2) ? w2 : w3;
    int i = blockIdx.x * blockDim.x + threadIdx.x;
    float4 v = src[i];
    union { uint2 u; __half b[4]; } H;
    H.b[0] = __float2half(v.x); H.b[1] = __float2half(v.y);
    H.b[2] = __float2half(v.z); H.b[3] = __float2half(v.w);
    dst[(size_t)wsel * 65536 + i] = H.u;
}

// ---------------------------------------------------------------------------
// Per-pixel attention: 64 threads per pixel, 2 pixels per 128-thread block.
// q' stored fp32 (2 broadcast LDS.128 per e, no F2FP in stage-2 inner loop).
// exp via degree-9 Taylor on the FMA pipe (no MUFU; softmax shift-invariant,
// scores bounded). sT fp16 pitch 66. 1/Z and v+v doubling folded into svT.
// scr[b, e*64 + n/64, (n%64)*8 + h] = 2*out[b,n,h,e], fp16.
// ---------------------------------------------------------------------------
#define PQ 68

struct __align__(16) PixS {
    float q[8 * PQ];
    float k[8 * PQ];
    float v[8 * PQ];
    float rn[24];
    float sA[64];
    float qT[64 * 8];      // q'[e][h], 32B rows
    float svT[64 * 8];     // 2/Z_d * v[h][d] at svT[d*8+h]
    __half sT[64 * 66];    // exp(S)[e*66 + d]
};

__global__ __launch_bounds__(128) void attn_kernel(
    const __half* __restrict__ QKV, __half* __restrict__ scr)
{
    __shared__ PixS ps[2];
    const int t = threadIdx.x;
    const int gsel = t >> 6, t6 = t & 63;
    PixS& S = ps[gsel];
    const int pix = blockIdx.x * 2 + gsel;

    {
        const uint4* src = (const uint4*)(QKV + (size_t)pix * NQKV);
#pragma unroll
        for (int j = 0; j < 3; j++) {
            int i = j * 64 + t6;
            union { uint4 u; __half h[8]; } U;
            U.u = src[i];
            float* rowp = (j == 0 ? S.q : j == 1 ? S.k : S.v)
                        + (t6 >> 3) * PQ + (t6 & 7) * 8;
            ((float4*)rowp)[0] = make_float4(
                __half2float(U.h[0]), __half2float(U.h[1]),
                __half2float(U.h[2]), __half2float(U.h[3]));
            ((float4*)rowp)[1] = make_float4(
                __half2float(U.h[4]), __half2float(U.h[5]),
                __half2float(U.h[6]), __half2float(U.h[7]));
        }
    }
    __syncthreads();

    if (t6 < 24) {
        int which = t6 >> 3, h = t6 & 7;
        const float* p = (which == 0 ? S.q : which == 1 ? S.k : S.v) + h * PQ;
        float s = 0.f;
#pragma unroll
        for (int i = 0; i < 16; i++) {
            float4 x = ((const float4*)p)[i];
            s = fmaf(x.x, x.x, fmaf(x.y, x.y, fmaf(x.z, x.z, fmaf(x.w, x.w, s))));
        }
        S.rn[t6] = 1.f / fmaxf(sqrtf(s), 1e-12f);
    }
    __syncthreads();

    {
        int h = t6 >> 3, g = t6 & 7;
        const float4* ph = (const float4*)(S.v + h * PQ);
        const float4* pg = (const float4*)(S.v + g * PQ);
        float s = 0.f;
#pragma unroll
        for (int i = 0; i < 16; i++) {
            float4 a = ph[i], b = pg[i];
            s = fmaf(a.x, b.x, fmaf(a.y, b.y, fmaf(a.z, b.z, fmaf(a.w, b.w, s))));
        }
        S.sA[t6] = s * S.rn[16 + h] * S.rn[16 + g];
    }
    __syncthreads();

    if (t6 < 8) {
        float e[8], sum = 0.f;
#pragma unroll
        for (int g = 0; g < 8; g++) { e[g] = __expf(S.sA[t6 * 8 + g]); sum += e[g]; }
        float inv = 1.f / sum;
#pragma unroll
        for (int g = 0; g < 8; g++) S.sA[t6 * 8 + g] = e[g] * inv;
    }
    __syncthreads();

    // head mix at column d = t6: q' -> fp32 qT, k' -> regs
    float k2[8];
    {
        const int d = t6;
        float qc[8], kc[8];
#pragma unroll
        for (int g = 0; g < 8; g++) {
            qc[g] = S.q[g * PQ + d] * S.rn[g];
            kc[g] = S.k[g * PQ + d] * S.rn[8 + g];
        }
        float4 qa, qb;
        float q2[8];
#pragma unroll
        for (int h = 0; h < 8; h++) {
            float s1 = 0.f, s2 = 0.f;
#pragma unroll
            for (int g = 0; g < 8; g++) {
                s1 = fmaf(S.sA[h * 8 + g], qc[g], s1);
                s2 = fmaf(S.sA[h * 8 + g], kc[g], s2);
            }
            q2[h] = s1;
            k2[h] = s2;
        }
        qa = make_float4(q2[0], q2[1], q2[2], q2[3]);
        qb = make_float4(q2[4], q2[5], q2[6], q2[7]);
        *(float4*)(S.qT + d * 8)     = qa;
        *(float4*)(S.qT + d * 8 + 4) = qb;
    }
    __syncthreads();

    // stage 2, thread d: polynomial exp, single pass
    {
        const int d = t6;
        float Z = 0.f;
#pragma unroll 8
        for (int e = 0; e < 64; e++) {
            const float4* qp = (const float4*)(S.qT + e * 8);   // broadcast
            float4 f0 = qp[0], f1 = qp[1];
            float s = k2[0] * f0.x;
            s = fmaf(k2[1], f0.y, s);
            s = fmaf(k2[2], f0.z, s);
            s = fmaf(k2[3], f0.w, s);
            s = fmaf(k2[4], f1.x, s);
            s = fmaf(k2[5], f1.y, s);
            s = fmaf(k2[6], f1.z, s);
            s = fmaf(k2[7], f1.w, s);
            float p = fmaf(2.7557319e-6f, s, 2.4801587e-5f);
            p = fmaf(p, s, 1.9841270e-4f);
            p = fmaf(p, s, 1.3888889e-3f);
            p = fmaf(p, s, 8.3333333e-3f);
            p = fmaf(p, s, 4.1666667e-2f);
            p = fmaf(p, s, 1.6666667e-1f);
            p = fmaf(p, s, 0.5f);
            p = fmaf(p, s, 1.0f);
            p = fmaf(p, s, 1.0f);
            Z += p;
            S.sT[e * 66 + d] = __float2half(p);
        }
        float inv2 = 2.f / Z;
        float4 a, b;
        a.x = S.v[0 * PQ + d] * inv2;
        a.y = S.v[1 * PQ + d] * inv2;
        a.z = S.v[2 * PQ + d] * inv2;
        a.w = S.v[3 * PQ + d] * inv2;
        b.x = S.v[4 * PQ + d] * inv2;
        b.y = S.v[5 * PQ + d] * inv2;
        b.z = S.v[6 * PQ + d] * inv2;
        b.w = S.v[7 * PQ + d] * inv2;
        *(float4*)(S.svT + d * 8) = a;
        *(float4*)(S.svT + d * 8 + 4) = b;
    }
    __syncthreads();

    // output, thread e
    {
        const int e = t6;
        float o[8] = {0, 0, 0, 0, 0, 0, 0, 0};
        const __half2* prow = (const __half2*)(S.sT + e * 66);
#pragma unroll 8
        for (int dd = 0; dd < 32; dd++) {
            float2 a = __half22float2(prow[dd]);
            const float4* v0 = (const float4*)(S.svT + (2 * dd) * 8);
            float4 va = v0[0], vb = v0[1];
            o[0] = fmaf(a.x, va.x, o[0]);
            o[1] = fmaf(a.x, va.y, o[1]);
            o[2] = fmaf(a.x, va.z, o[2]);
            o[3] = fmaf(a.x, va.w, o[3]);
            o[4] = fmaf(a.x, vb.x, o[4]);
            o[5] = fmaf(a.x, vb.y, o[5]);
            o[6] = fmaf(a.x, vb.z, o[6]);
            o[7] = fmaf(a.x, vb.w, o[7]);
            const float4* v1 = (const float4*)(S.svT + (2 * dd + 1) * 8);
            va = v1[0]; vb = v1[1];
            o[0] = fmaf(a.y, va.x, o[0]);
            o[1] = fmaf(a.y, va.y, o[1]);
            o[2] = fmaf(a.y, va.z, o[2]);
            o[3] = fmaf(a.y, va.w, o[3]);
            o[4] = fmaf(a.y, vb.x, o[4]);
            o[5] = fmaf(a.y, vb.y, o[5]);
            o[6] = fmaf(a.y, vb.z, o[6]);
            o[7] = fmaf(a.y, vb.w, o[7]);
        }
        const int b = pix >> 12;
        const int n = pix & 4095;
        const size_t off =
            ((size_t)(b * 4096 + e * 64 + (n >> 6))) * CDIM + (n & 63) * 8;
        union { uint4 u; __half hh[8]; } O;
#pragma unroll
        for (int h = 0; h < 8; h++) O.hh[h] = __float2half(o[h]);
        *(uint4*)(scr + off) = O.u;
    }
}

// ---------------------------------------------------------------------------
extern "C" void kernel_launch(void* const* d_in, const int* in_sizes, int n_in,
                              void* d_out, int out_size)
{
    const float* x     = (const float*)d_in[0];
    const float* Wq    = (const float*)d_in[1];
    const float* Wk    = (const float*)d_in[2];
    const float* Wv    = (const float*)d_in[3];
    // d_in[4] = conv_w: dead in the reference
    const float* projw = (const float*)d_in[5];
    const float* projb = (const float*)d_in[6];
    float* out = (float*)d_out;

    cudaFuncSetAttribute(gemm_f16<true>, cudaFuncAttributeMaxDynamicSharedMemorySize, GSMEM);
    cudaFuncSetAttribute(gemm_f16<false>, cudaFuncAttributeMaxDynamicSharedMemorySize, GSMEM);

    __half *x16, *s16, *w16, *qkv16;
    cudaGetSymbolAddress((void**)&x16, g_x16);
    cudaGetSymbolAddress((void**)&s16, g_s16);
    cudaGetSymbolAddress((void**)&w16, g_w16);
    cudaGetSymbolAddress((void**)&qkv16, g_qkv16);

    cvt_x<<<MTOT * CDIM / 4 / 256, 256>>>((const float4*)x, (uint2*)x16, MTOT * CDIM / 4);
    cvt_w<<<dim3(256, 4), 256>>>(
        (const float4*)Wq, (const float4*)Wk, (const float4*)Wv,
        (const float4*)projw, (uint2*)w16);

    // fused QKV GEMM: [16384,512] x [1536,512]^T -> fp16 [16384,1536]
    gemm_f16<true><<<dim3(NQKV / 256, MTOT / 128), 256, GSMEM>>>(
        x16, w16, nullptr, qkv16, NQKV);

    attn_kernel<<<MTOT / 2, 128>>>(qkv16, s16);

    // proj GEMM: [16384,512] x [512,512]^T -> fp32 out
    gemm_f16<false><<<dim3(CDIM / 256, MTOT / 128), 256, GSMEM>>>(
        s16, w16 + 3 * CDIM * CDIM, projb, out, CDIM);
}

// round 8
// speedup vs baseline: 1.0594x; 1.0594x over previous
#include <cuda_runtime.h>
#include <cuda_fp16.h>
#include <stdint.h>
#include <math.h>

#define MTOT 16384
#define CDIM 512
#define NQKV 1536

// ---------------------------------------------------------------------------
// Scratch (static __device__: no allocations allowed)
// ---------------------------------------------------------------------------
__device__ __half g_x16[MTOT * CDIM];
__device__ __half g_qkv16[(size_t)MTOT * NQKV];
__device__ __half g_s16[MTOT * CDIM];
__device__ __half g_w16[4 * CDIM * CDIM];   // Wq, Wk, Wv, proj

// ---------------------------------------------------------------------------
// PTX helpers (arch-portable)
// ---------------------------------------------------------------------------
__device__ __forceinline__ uint32_t smem_u32(const void* p) {
    uint32_t a;
    asm("{ .reg .u64 t; cvta.to.shared.u64 t, %1; cvt.u32.u64 %0, t; }"
        : "=r"(a) : "l"(p));
    return a;
}
__device__ __forceinline__ void ldm_x4(uint32_t* r, uint32_t addr) {
    asm volatile("ldmatrix.sync.aligned.m8n8.x4.shared.b16 {%0,%1,%2,%3}, [%4];"
                 : "=r"(r[0]), "=r"(r[1]), "=r"(r[2]), "=r"(r[3]) : "r"(addr));
}
__device__ __forceinline__ void mma_f16(float* d, const uint32_t* a, const uint32_t* b) {
    asm volatile(
        "mma.sync.aligned.m16n8k16.row.col.f32.f16.f16.f32 "
        "{%0,%1,%2,%3}, {%4,%5,%6,%7}, {%8,%9}, {%0,%1,%2,%3};"
        : "+f"(d[0]), "+f"(d[1]), "+f"(d[2]), "+f"(d[3])
        : "r"(a[0]), "r"(a[1]), "r"(a[2]), "r"(a[3]), "r"(b[0]), "r"(b[1]));
}
__device__ __forceinline__ void cp_async16(uint32_t dst, const void* src) {
    asm volatile("cp.async.cg.shared.global [%0], [%1], 16;" :: "r"(dst), "l"(src));
}
#define CP_COMMIT() asm volatile("cp.async.commit_group;" ::: "memory")
#define CP_WAIT(N)  asm volatile("cp.async.wait_group %0;" :: "n"(N) : "memory")

// ---------------------------------------------------------------------------
// fp16 GEMM: C[m,n] = sum_k A[m,k] * B[n,k] (+bias)
// BM=128, BN=128, BK=32, 256 threads (8 warps, 2x4, warp tile 64x32),
// 3-stage cp.async, 2 CTAs/SM (barrier interleave for latency hiding).
// ---------------------------------------------------------------------------
#define PITCH 40
#define SH ((128 + 128) * PITCH)           // halfs per stage = 10240
#define OFF_B (128 * PITCH)
#define GSMEM (3 * SH * 2)                 // 61440 B

template <bool HOUT>
__global__ __launch_bounds__(256, 2)
void gemm_f16(const __half* __restrict__ A, const __half* __restrict__ B,
              const float* __restrict__ bias, void* __restrict__ Cv, int ldc)
{
    extern __shared__ __align__(16) __half sm[];
    const int tid = threadIdx.x;
    const int wid = tid >> 5, L = tid & 31;
    const int m0 = blockIdx.y * 128;
    const int n0 = blockIdx.x * 128;
    const int wm = (wid >> 2) * 64;
    const int wn = (wid & 3) * 32;
    const uint32_t sb = smem_u32(sm);

    const __half* Ab = A + (size_t)m0 * CDIM;
    const __half* Bb = B + (size_t)n0 * CDIM;

    float acc[4][4][4];
#pragma unroll
    for (int i = 0; i < 4; i++)
#pragma unroll
        for (int j = 0; j < 4; j++)
#pragma unroll
            for (int q = 0; q < 4; q++) acc[i][j][q] = 0.f;

    const int aRow = L & 15, aK = (L >> 4) * 8;
    const int bRowL = (L & 7) + ((L & 16) ? 8 : 0);
    const int bK = ((L >> 3) & 1) * 8;
    const int lr = tid >> 1, lc = tid & 1;   // 128 rows x 2 threads x 2 chunks

    auto load_stage = [&](int stage, int k0) {
        const uint32_t s0 = sb + (uint32_t)stage * SH * 2;
        // A: 128 rows x 4 chunks = 512 cp; 2 per thread
        cp_async16(s0 + (uint32_t)(lr * PITCH + lc * 8) * 2,
                   Ab + (size_t)lr * CDIM + k0 + lc * 8);
        cp_async16(s0 + (uint32_t)(lr * PITCH + (lc + 2) * 8) * 2,
                   Ab + (size_t)lr * CDIM + k0 + (lc + 2) * 8);
        // B: same
        cp_async16(s0 + OFF_B * 2 + (uint32_t)(lr * PITCH + lc * 8) * 2,
                   Bb + (size_t)lr * CDIM + k0 + lc * 8);
        cp_async16(s0 + OFF_B * 2 + (uint32_t)(lr * PITCH + (lc + 2) * 8) * 2,
                   Bb + (size_t)lr * CDIM + k0 + (lc + 2) * 8);
    };

    load_stage(0, 0);  CP_COMMIT();
    load_stage(1, 32); CP_COMMIT();

    const int NIT = CDIM / 32;   // 16
    for (int s = 0; s < NIT; s++) {
        CP_WAIT(1);
        __syncthreads();
        if (s + 2 < NIT) load_stage((s + 2) % 3, (s + 2) * 32);
        CP_COMMIT();

        const uint32_t pA = sb + (uint32_t)(s % 3) * SH * 2;
        const uint32_t pB = pA + OFF_B * 2;

#pragma unroll
        for (int kk = 0; kk < 32; kk += 16) {
            uint32_t ah[4][4], bh[4][2];
#pragma unroll
            for (int mi = 0; mi < 4; mi++) {
                uint32_t ro = (uint32_t)((wm + mi * 16 + aRow) * PITCH + kk + aK) * 2;
                ldm_x4(ah[mi], pA + ro);
            }
#pragma unroll
            for (int nb = 0; nb < 2; nb++) {
                uint32_t ro = (uint32_t)((wn + nb * 16 + bRowL) * PITCH + kk + bK) * 2;
                uint32_t th[4];
                ldm_x4(th, pB + ro);
                bh[nb * 2][0] = th[0];     bh[nb * 2][1] = th[1];
                bh[nb * 2 + 1][0] = th[2]; bh[nb * 2 + 1][1] = th[3];
            }
#pragma unroll
            for (int mi = 0; mi < 4; mi++)
#pragma unroll
                for (int ni = 0; ni < 4; ni++)
                    mma_f16(acc[mi][ni], ah[mi], bh[ni]);
        }
        __syncthreads();
    }

    const int cr = L >> 2, cc = (L & 3) * 2;
#pragma unroll
    for (int mi = 0; mi < 4; mi++) {
#pragma unroll
        for (int ni = 0; ni < 4; ni++) {
            int row = m0 + wm + mi * 16 + cr;
            int col = n0 + wn + ni * 8 + cc;
            float b0 = 0.f, b1 = 0.f;
            if (bias) { b0 = bias[col]; b1 = bias[col + 1]; }
            if (HOUT) {
                __half* C = (__half*)Cv;
                *(__half2*)&C[(size_t)row * ldc + col] =
                    __floats2half2_rn(acc[mi][ni][0] + b0, acc[mi][ni][1] + b1);
                *(__half2*)&C[(size_t)(row + 8) * ldc + col] =
                    __floats2half2_rn(acc[mi][ni][2] + b0, acc[mi][ni][3] + b1);
            } else {
                float* C = (float*)Cv;
                *(float2*)&C[(size_t)row * ldc + col] =
                    make_float2(acc[mi][ni][0] + b0, acc[mi][ni][1] + b1);
                *(float2*)&C[(size_t)(row + 8) * ldc + col] =
                    make_float2(acc[mi][ni][2] + b0, acc[mi][ni][3] + b1);
            }
        }
    }
}

// ---------------------------------------------------------------------------
// fp32 -> fp16 converts
// ---------------------------------------------------------------------------
__global__ void cvt_x(const float4* __restrict__ src, uint2* __restrict__ dst, int n4)
{
    int i = blockIdx.x * blockDim.x + threadIdx.x;
    if (i >= n4) return;
    float4 v = src[i];
    union { uint2 u; __half b[4]; } H;
    H.b[0] = __float2half(v.x); H.b[1] = __float2half(v.y);
    H.b[2] = __float2half(v.z); H.b[3] = __float2half(v.w);
    dst[i] = H.u;
}

__global__ void cvt_w(const float4* __restrict__ w0, const float4* __restrict__ w1,
                      const float4* __restrict__ w2, const float4* __restrict__ w3,
                      uint2* __restrict__ dst)
{
    int wsel = blockIdx.y;
    const float4* src = (wsel == 0) ? w0 : (wsel == 1) ? w1 : (wsel == 2) ? w2 : w3;
    int i = blockIdx.x * blockDim.x + threadIdx.x;
    float4 v = src[i];
    union { uint2 u; __half b[4]; } H;
    H.b[0] = __float2half(v.x); H.b[1] = __float2half(v.y);
    H.b[2] = __float2half(v.z); H.b[3] = __float2half(v.w);
    dst[(size_t)wsel * 65536 + i] = H.u;
}

// ---------------------------------------------------------------------------
// Per-pixel attention (R6 layout): 64 threads/pixel, 2 pixels/block.
// q' fp16 (one broadcast LDS.128 per e), __expf (MUFU under-subscribed;
// fewer issue slots than polynomial), single-pass softmax without max
// (scores bounded, softmax shift-invariant), sT fp16 pitch 66,
// 1/Z and v+v doubling folded into svT.
// scr[b, e*64 + n/64, (n%64)*8 + h] = 2*out[b,n,h,e], fp16.
// ---------------------------------------------------------------------------
#define PQ 68

struct __align__(16) PixS {
    float q[8 * PQ];
    float k[8 * PQ];
    float v[8 * PQ];
    float rn[24];
    float sA[64];
    __half qT[64 * 8];     // q'[e][h], 16B rows
    float svT[64 * 8];     // 2/Z_d * v[h][d] at svT[d*8+h]
    __half sT[64 * 66];    // exp(S)[e*66 + d]
};

__global__ __launch_bounds__(128) void attn_kernel(
    const __half* __restrict__ QKV, __half* __restrict__ scr)
{
    __shared__ PixS ps[2];
    const int t = threadIdx.x;
    const int gsel = t >> 6, t6 = t & 63;
    PixS& S = ps[gsel];
    const int pix = blockIdx.x * 2 + gsel;

    {
        const uint4* src = (const uint4*)(QKV + (size_t)pix * NQKV);
#pragma unroll
        for (int j = 0; j < 3; j++) {
            int i = j * 64 + t6;
            union { uint4 u; __half h[8]; } U;
            U.u = src[i];
            float* rowp = (j == 0 ? S.q : j == 1 ? S.k : S.v)
                        + (t6 >> 3) * PQ + (t6 & 7) * 8;
            ((float4*)rowp)[0] = make_float4(
                __half2float(U.h[0]), __half2float(U.h[1]),
                __half2float(U.h[2]), __half2float(U.h[3]));
            ((float4*)rowp)[1] = make_float4(
                __half2float(U.h[4]), __half2float(U.h[5]),
                __half2float(U.h[6]), __half2float(U.h[7]));
        }
    }
    __syncthreads();

    if (t6 < 24) {
        int which = t6 >> 3, h = t6 & 7;
        const float* p = (which == 0 ? S.q : which == 1 ? S.k : S.v) + h * PQ;
        float s = 0.f;
#pragma unroll
        for (int i = 0; i < 16; i++) {
            float4 x = ((const float4*)p)[i];
            s = fmaf(x.x, x.x, fmaf(x.y, x.y, fmaf(x.z, x.z, fmaf(x.w, x.w, s))));
        }
        S.rn[t6] = 1.f / fmaxf(sqrtf(s), 1e-12f);
    }
    __syncthreads();

    {
        int h = t6 >> 3, g = t6 & 7;
        const float4* ph = (const float4*)(S.v + h * PQ);
        const float4* pg = (const float4*)(S.v + g * PQ);
        float s = 0.f;
#pragma unroll
        for (int i = 0; i < 16; i++) {
            float4 a = ph[i], b = pg[i];
            s = fmaf(a.x, b.x, fmaf(a.y, b.y, fmaf(a.z, b.z, fmaf(a.w, b.w, s))));
        }
        S.sA[t6] = s * S.rn[16 + h] * S.rn[16 + g];
    }
    __syncthreads();

    if (t6 < 8) {
        float e[8], sum = 0.f;
#pragma unroll
        for (int g = 0; g < 8; g++) { e[g] = __expf(S.sA[t6 * 8 + g]); sum += e[g]; }
        float inv = 1.f / sum;
#pragma unroll
        for (int g = 0; g < 8; g++) S.sA[t6 * 8 + g] = e[g] * inv;
    }
    __syncthreads();

    // head mix at column d = t6: q' -> fp16 qT, k' -> regs
    float k2[8];
    {
        const int d = t6;
        float qc[8], kc[8];
#pragma unroll
        for (int g = 0; g < 8; g++) {
            qc[g] = S.q[g * PQ + d] * S.rn[g];
            kc[g] = S.k[g * PQ + d] * S.rn[8 + g];
        }
        union { uint4 u; __half hh[8]; } QP;
#pragma unroll
        for (int h = 0; h < 8; h++) {
            float s1 = 0.f, s2 = 0.f;
#pragma unroll
            for (int g = 0; g < 8; g++) {
                s1 = fmaf(S.sA[h * 8 + g], qc[g], s1);
                s2 = fmaf(S.sA[h * 8 + g], kc[g], s2);
            }
            QP.hh[h] = __float2half(s1);
            k2[h] = s2;
        }
        *(uint4*)(S.qT + d * 8) = QP.u;
    }
    __syncthreads();

    // stage 2, thread d: __expf, single pass
    {
        const int d = t6;
        float Z = 0.f;
#pragma unroll 8
        for (int e = 0; e < 64; e++) {
            union { uint4 u; __half2 h2[4]; } U;
            U.u = *(const uint4*)(S.qT + e * 8);      // broadcast
            float2 f0 = __half22float2(U.h2[0]);
            float2 f1 = __half22float2(U.h2[1]);
            float2 f2 = __half22float2(U.h2[2]);
            float2 f3 = __half22float2(U.h2[3]);
            float s = k2[0] * f0.x;
            s = fmaf(k2[1], f0.y, s);
            s = fmaf(k2[2], f1.x, s);
            s = fmaf(k2[3], f1.y, s);
            s = fmaf(k2[4], f2.x, s);
            s = fmaf(k2[5], f2.y, s);
            s = fmaf(k2[6], f3.x, s);
            s = fmaf(k2[7], f3.y, s);
            float p = __expf(s);
            Z += p;
            S.sT[e * 66 + d] = __float2half(p);
        }
        float inv2 = 2.f / Z;
        float4 a, b;
        a.x = S.v[0 * PQ + d] * inv2;
        a.y = S.v[1 * PQ + d] * inv2;
        a.z = S.v[2 * PQ + d] * inv2;
        a.w = S.v[3 * PQ + d] * inv2;
        b.x = S.v[4 * PQ + d] * inv2;
        b.y = S.v[5 * PQ + d] * inv2;
        b.z = S.v[6 * PQ + d] * inv2;
        b.w = S.v[7 * PQ + d] * inv2;
        *(float4*)(S.svT + d * 8) = a;
        *(float4*)(S.svT + d * 8 + 4) = b;
    }
    __syncthreads();

    // output, thread e
    {
        const int e = t6;
        float o[8] = {0, 0, 0, 0, 0, 0, 0, 0};
        const __half2* prow = (const __half2*)(S.sT + e * 66);
#pragma unroll 8
        for (int dd = 0; dd < 32; dd++) {
            float2 a = __half22float2(prow[dd]);
            const float4* v0 = (const float4*)(S.svT + (2 * dd) * 8);
            float4 va = v0[0], vb = v0[1];
            o[0] = fmaf(a.x, va.x, o[0]);
            o[1] = fmaf(a.x, va.y, o[1]);
            o[2] = fmaf(a.x, va.z, o[2]);
            o[3] = fmaf(a.x, va.w, o[3]);
            o[4] = fmaf(a.x, vb.x, o[4]);
            o[5] = fmaf(a.x, vb.y, o[5]);
            o[6] = fmaf(a.x, vb.z, o[6]);
            o[7] = fmaf(a.x, vb.w, o[7]);
            const float4* v1 = (const float4*)(S.svT + (2 * dd + 1) * 8);
            va = v1[0]; vb = v1[1];
            o[0] = fmaf(a.y, va.x, o[0]);
            o[1] = fmaf(a.y, va.y, o[1]);
            o[2] = fmaf(a.y, va.z, o[2]);
            o[3] = fmaf(a.y, va.w, o[3]);
            o[4] = fmaf(a.y, vb.x, o[4]);
            o[5] = fmaf(a.y, vb.y, o[5]);
            o[6] = fmaf(a.y, vb.z, o[6]);
            o[7] = fmaf(a.y, vb.w, o[7]);
        }
        const int b = pix >> 12;
        const int n = pix & 4095;
        const size_t off =
            ((size_t)(b * 4096 + e * 64 + (n >> 6))) * CDIM + (n & 63) * 8;
        union { uint4 u; __half hh[8]; } O;
#pragma unroll
        for (int h = 0; h < 8; h++) O.hh[h] = __float2half(o[h]);
        *(uint4*)(scr + off) = O.u;
    }
}

// ---------------------------------------------------------------------------
extern "C" void kernel_launch(void* const* d_in, const int* in_sizes, int n_in,
                              void* d_out, int out_size)
{
    const float* x     = (const float*)d_in[0];
    const float* Wq    = (const float*)d_in[1];
    const float* Wk    = (const float*)d_in[2];
    const float* Wv    = (const float*)d_in[3];
    // d_in[4] = conv_w: dead in the reference
    const float* projw = (const float*)d_in[5];
    const float* projb = (const float*)d_in[6];
    float* out = (float*)d_out;

    cudaFuncSetAttribute(gemm_f16<true>, cudaFuncAttributeMaxDynamicSharedMemorySize, GSMEM);
    cudaFuncSetAttribute(gemm_f16<false>, cudaFuncAttributeMaxDynamicSharedMemorySize, GSMEM);

    __half *x16, *s16, *w16, *qkv16;
    cudaGetSymbolAddress((void**)&x16, g_x16);
    cudaGetSymbolAddress((void**)&s16, g_s16);
    cudaGetSymbolAddress((void**)&w16, g_w16);
    cudaGetSymbolAddress((void**)&qkv16, g_qkv16);

    cvt_x<<<MTOT * CDIM / 4 / 256, 256>>>((const float4*)x, (uint2*)x16, MTOT * CDIM / 4);
    cvt_w<<<dim3(256, 4), 256>>>(
        (const float4*)Wq, (const float4*)Wk, (const float4*)Wv,
        (const float4*)projw, (uint2*)w16);

    // fused QKV GEMM: [16384,512] x [1536,512]^T -> fp16 [16384,1536]
    gemm_f16<true><<<dim3(NQKV / 128, MTOT / 128), 256, GSMEM>>>(
        x16, w16, nullptr, qkv16, NQKV);

    attn_kernel<<<MTOT / 2, 128>>>(qkv16, s16);

    // proj GEMM: [16384,512] x [512,512]^T -> fp32 out
    gemm_f16<false><<<dim3(CDIM / 128, MTOT / 128), 256, GSMEM>>>(
        s16, w16 + 3 * CDIM * CDIM, projb, out, CDIM);
}

// round 9
// speedup vs baseline: 1.2917x; 1.2193x over previous
#include <cuda_runtime.h>
#include <cuda_fp16.h>
#include <stdint.h>
#include <math.h>

#define MTOT 16384
#define CDIM 512
#define NQKV 1536

// ---------------------------------------------------------------------------
// Scratch (static __device__: no allocations allowed)
// ---------------------------------------------------------------------------
__device__ __half g_x16[MTOT * CDIM];
__device__ __half g_qkv16[(size_t)MTOT * NQKV];
__device__ __half g_s16[MTOT * CDIM];
__device__ __half g_w16[4 * CDIM * CDIM];   // Wq, Wk, Wv, proj

// ---------------------------------------------------------------------------
// PTX helpers (arch-portable)
// ---------------------------------------------------------------------------
__device__ __forceinline__ uint32_t smem_u32(const void* p) {
    uint32_t a;
    asm("{ .reg .u64 t; cvta.to.shared.u64 t, %1; cvt.u32.u64 %0, t; }"
        : "=r"(a) : "l"(p));
    return a;
}
__device__ __forceinline__ void ldm_x4(uint32_t* r, uint32_t addr) {
    asm volatile("ldmatrix.sync.aligned.m8n8.x4.shared.b16 {%0,%1,%2,%3}, [%4];"
                 : "=r"(r[0]), "=r"(r[1]), "=r"(r[2]), "=r"(r[3]) : "r"(addr));
}
__device__ __forceinline__ void mma_f16(float* d, const uint32_t* a, const uint32_t* b) {
    asm volatile(
        "mma.sync.aligned.m16n8k16.row.col.f32.f16.f16.f32 "
        "{%0,%1,%2,%3}, {%4,%5,%6,%7}, {%8,%9}, {%0,%1,%2,%3};"
        : "+f"(d[0]), "+f"(d[1]), "+f"(d[2]), "+f"(d[3])
        : "r"(a[0]), "r"(a[1]), "r"(a[2]), "r"(a[3]), "r"(b[0]), "r"(b[1]));
}
__device__ __forceinline__ void mma_f16_k8(float* d, uint32_t a0, uint32_t a1, uint32_t b0) {
    asm volatile(
        "mma.sync.aligned.m16n8k8.row.col.f32.f16.f16.f32 "
        "{%0,%1,%2,%3}, {%4,%5}, {%6}, {%0,%1,%2,%3};"
        : "+f"(d[0]), "+f"(d[1]), "+f"(d[2]), "+f"(d[3])
        : "r"(a0), "r"(a1), "r"(b0));
}
__device__ __forceinline__ void cp_async16(uint32_t dst, const void* src) {
    asm volatile("cp.async.cg.shared.global [%0], [%1], 16;" :: "r"(dst), "l"(src));
}
#define CP_COMMIT() asm volatile("cp.async.commit_group;" ::: "memory")
#define CP_WAIT(N)  asm volatile("cp.async.wait_group %0;" :: "n"(N) : "memory")

__device__ __forceinline__ uint32_t pack_h2(float a, float b) {
    __half2 h = __floats2half2_rn(a, b);
    return *(uint32_t*)&h;
}

// ---------------------------------------------------------------------------
// fp16 GEMM (unchanged from R8): BM=128, BN=128, BK=32, 256 threads,
// 3-stage cp.async, 2 CTAs/SM.
// ---------------------------------------------------------------------------
#define PITCH 40
#define SH ((128 + 128) * PITCH)
#define OFF_B (128 * PITCH)
#define GSMEM (3 * SH * 2)

template <bool HOUT>
__global__ __launch_bounds__(256, 2)
void gemm_f16(const __half* __restrict__ A, const __half* __restrict__ B,
              const float* __restrict__ bias, void* __restrict__ Cv, int ldc)
{
    extern __shared__ __align__(16) __half sm[];
    const int tid = threadIdx.x;
    const int wid = tid >> 5, L = tid & 31;
    const int m0 = blockIdx.y * 128;
    const int n0 = blockIdx.x * 128;
    const int wm = (wid >> 2) * 64;
    const int wn = (wid & 3) * 32;
    const uint32_t sb = smem_u32(sm);

    const __half* Ab = A + (size_t)m0 * CDIM;
    const __half* Bb = B + (size_t)n0 * CDIM;

    float acc[4][4][4];
#pragma unroll
    for (int i = 0; i < 4; i++)
#pragma unroll
        for (int j = 0; j < 4; j++)
#pragma unroll
            for (int q = 0; q < 4; q++) acc[i][j][q] = 0.f;

    const int aRow = L & 15, aK = (L >> 4) * 8;
    const int bRowL = (L & 7) + ((L & 16) ? 8 : 0);
    const int bK = ((L >> 3) & 1) * 8;
    const int lr = tid >> 1, lc = tid & 1;

    auto load_stage = [&](int stage, int k0) {
        const uint32_t s0 = sb + (uint32_t)stage * SH * 2;
        cp_async16(s0 + (uint32_t)(lr * PITCH + lc * 8) * 2,
                   Ab + (size_t)lr * CDIM + k0 + lc * 8);
        cp_async16(s0 + (uint32_t)(lr * PITCH + (lc + 2) * 8) * 2,
                   Ab + (size_t)lr * CDIM + k0 + (lc + 2) * 8);
        cp_async16(s0 + OFF_B * 2 + (uint32_t)(lr * PITCH + lc * 8) * 2,
                   Bb + (size_t)lr * CDIM + k0 + lc * 8);
        cp_async16(s0 + OFF_B * 2 + (uint32_t)(lr * PITCH + (lc + 2) * 8) * 2,
                   Bb + (size_t)lr * CDIM + k0 + (lc + 2) * 8);
    };

    load_stage(0, 0);  CP_COMMIT();
    load_stage(1, 32); CP_COMMIT();

    const int NIT = CDIM / 32;
    for (int s = 0; s < NIT; s++) {
        CP_WAIT(1);
        __syncthreads();
        if (s + 2 < NIT) load_stage((s + 2) % 3, (s + 2) * 32);
        CP_COMMIT();

        const uint32_t pA = sb + (uint32_t)(s % 3) * SH * 2;
        const uint32_t pB = pA + OFF_B * 2;

#pragma unroll
        for (int kk = 0; kk < 32; kk += 16) {
            uint32_t ah[4][4], bh[4][2];
#pragma unroll
            for (int mi = 0; mi < 4; mi++) {
                uint32_t ro = (uint32_t)((wm + mi * 16 + aRow) * PITCH + kk + aK) * 2;
                ldm_x4(ah[mi], pA + ro);
            }
#pragma unroll
            for (int nb = 0; nb < 2; nb++) {
                uint32_t ro = (uint32_t)((wn + nb * 16 + bRowL) * PITCH + kk + bK) * 2;
                uint32_t th[4];
                ldm_x4(th, pB + ro);
                bh[nb * 2][0] = th[0];     bh[nb * 2][1] = th[1];
                bh[nb * 2 + 1][0] = th[2]; bh[nb * 2 + 1][1] = th[3];
            }
#pragma unroll
            for (int mi = 0; mi < 4; mi++)
#pragma unroll
                for (int ni = 0; ni < 4; ni++)
                    mma_f16(acc[mi][ni], ah[mi], bh[ni]);
        }
        __syncthreads();
    }

    const int cr = L >> 2, cc = (L & 3) * 2;
#pragma unroll
    for (int mi = 0; mi < 4; mi++) {
#pragma unroll
        for (int ni = 0; ni < 4; ni++) {
            int row = m0 + wm + mi * 16 + cr;
            int col = n0 + wn + ni * 8 + cc;
            float b0 = 0.f, b1 = 0.f;
            if (bias) { b0 = bias[col]; b1 = bias[col + 1]; }
            if (HOUT) {
                __half* C = (__half*)Cv;
                *(__half2*)&C[(size_t)row * ldc + col] =
                    __floats2half2_rn(acc[mi][ni][0] + b0, acc[mi][ni][1] + b1);
                *(__half2*)&C[(size_t)(row + 8) * ldc + col] =
                    __floats2half2_rn(acc[mi][ni][2] + b0, acc[mi][ni][3] + b1);
            } else {
                float* C = (float*)Cv;
                *(float2*)&C[(size_t)row * ldc + col] =
                    make_float2(acc[mi][ni][0] + b0, acc[mi][ni][1] + b1);
                *(float2*)&C[(size_t)(row + 8) * ldc + col] =
                    make_float2(acc[mi][ni][2] + b0, acc[mi][ni][3] + b1);
            }
        }
    }
}

// ---------------------------------------------------------------------------
// fp32 -> fp16 converts
// ---------------------------------------------------------------------------
__global__ void cvt_x(const float4* __restrict__ src, uint2* __restrict__ dst, int n4)
{
    int i = blockIdx.x * blockDim.x + threadIdx.x;
    if (i >= n4) return;
    float4 v = src[i];
    union { uint2 u; __half b[4]; } H;
    H.b[0] = __float2half(v.x); H.b[1] = __float2half(v.y);
    H.b[2] = __float2half(v.z); H.b[3] = __float2half(v.w);
    dst[i] = H.u;
}

__global__ void cvt_w(const float4* __restrict__ w0, const float4* __restrict__ w1,
                      const float4* __restrict__ w2, const float4* __restrict__ w3,
                      uint2* __restrict__ dst)
{
    int wsel = blockIdx.y;
    const float4* src = (wsel == 0) ? w0 : (wsel == 1) ? w1 : (wsel == 2) ? w2 : w3;
    int i = blockIdx.x * blockDim.x + threadIdx.x;
    float4 v = src[i];
    union { uint2 u; __half b[4]; } H;
    H.b[0] = __float2half(v.x); H.b[1] = __float2half(v.y);
    H.b[2] = __float2half(v.z); H.b[3] = __float2half(v.w);
    dst[(size_t)wsel * 65536 + i] = H.u;
}

// ---------------------------------------------------------------------------
// Per-pixel attention with tensor-core stage2/output.
// 2 pixels per 128-thread block; per pixel 2 warps.
// Stage 2 as mma: S^T(e,d) = qT(e,:) . kT(d,:)  (K=8 heads), warp w owns
// e in [32w,32w+32), all 64 d. exp in regs, Z by shfl + cross-warp smem sum,
// 2/Z folded into v fragments, out^T(e,h) = P^T @ vhat via m16n8k16 with
// C->A fragment reuse. Direct half2 stores in scramble layout.
// ---------------------------------------------------------------------------
#define PQ 68

struct __align__(16) PixS {
    float q[8 * PQ];
    float k[8 * PQ];
    float v[8 * PQ];
    float rn[24];
    float sA[64];
    __align__(16) __half qT[64 * 8];   // q'[e][h]
    __align__(16) __half kT[64 * 8];   // k'[d][h]
    __align__(16) float zpart[2][64];  // per-warp Z partials
    __align__(16) float invb[64];      // 2 / Z_d
};

__global__ __launch_bounds__(128) void attn_kernel(
    const __half* __restrict__ QKV, __half* __restrict__ scr)
{
    __shared__ PixS ps[2];
    const int t = threadIdx.x;
    const int gsel = t >> 6, t6 = t & 63;
    PixS& S = ps[gsel];
    const int pix = blockIdx.x * 2 + gsel;

    // ---- load fp16 qkv -> fp32 padded smem ----
    {
        const uint4* src = (const uint4*)(QKV + (size_t)pix * NQKV);
#pragma unroll
        for (int j = 0; j < 3; j++) {
            int i = j * 64 + t6;
            union { uint4 u; __half h[8]; } U;
            U.u = src[i];
            float* rowp = (j == 0 ? S.q : j == 1 ? S.k : S.v)
                        + (t6 >> 3) * PQ + (t6 & 7) * 8;
            ((float4*)rowp)[0] = make_float4(
                __half2float(U.h[0]), __half2float(U.h[1]),
                __half2float(U.h[2]), __half2float(U.h[3]));
            ((float4*)rowp)[1] = make_float4(
                __half2float(U.h[4]), __half2float(U.h[5]),
                __half2float(U.h[6]), __half2float(U.h[7]));
        }
    }
    __syncthreads();

    // ---- inverse norms ----
    if (t6 < 24) {
        int which = t6 >> 3, h = t6 & 7;
        const float* p = (which == 0 ? S.q : which == 1 ? S.k : S.v) + h * PQ;
        float s = 0.f;
#pragma unroll
        for (int i = 0; i < 16; i++) {
            float4 x = ((const float4*)p)[i];
            s = fmaf(x.x, x.x, fmaf(x.y, x.y, fmaf(x.z, x.z, fmaf(x.w, x.w, s))));
        }
        S.rn[t6] = 1.f / fmaxf(sqrtf(s), 1e-12f);
    }
    __syncthreads();

    // ---- gram of normalized v ----
    {
        int h = t6 >> 3, g = t6 & 7;
        const float4* ph = (const float4*)(S.v + h * PQ);
        const float4* pg = (const float4*)(S.v + g * PQ);
        float s = 0.f;
#pragma unroll
        for (int i = 0; i < 16; i++) {
            float4 a = ph[i], b = pg[i];
            s = fmaf(a.x, b.x, fmaf(a.y, b.y, fmaf(a.z, b.z, fmaf(a.w, b.w, s))));
        }
        S.sA[t6] = s * S.rn[16 + h] * S.rn[16 + g];
    }
    __syncthreads();

    // ---- head-mix softmax rows (cosines bounded, no max needed) ----
    if (t6 < 8) {
        float e[8], sum = 0.f;
#pragma unroll
        for (int g = 0; g < 8; g++) { e[g] = __expf(S.sA[t6 * 8 + g]); sum += e[g]; }
        float inv = 1.f / sum;
#pragma unroll
        for (int g = 0; g < 8; g++) S.sA[t6 * 8 + g] *= 0.f, S.sA[t6 * 8 + g] = e[g] * inv;
    }
    __syncthreads();

    // ---- head mix at column d = t6: q' -> qT, k' -> kT (both fp16) ----
    {
        const int d = t6;
        float qc[8], kc[8];
#pragma unroll
        for (int g = 0; g < 8; g++) {
            qc[g] = S.q[g * PQ + d] * S.rn[g];
            kc[g] = S.k[g * PQ + d] * S.rn[8 + g];
        }
        union { uint4 u; __half hh[8]; } QP, KP;
#pragma unroll
        for (int h = 0; h < 8; h++) {
            float s1 = 0.f, s2 = 0.f;
#pragma unroll
            for (int g = 0; g < 8; g++) {
                s1 = fmaf(S.sA[h * 8 + g], qc[g], s1);
                s2 = fmaf(S.sA[h * 8 + g], kc[g], s2);
            }
            QP.hh[h] = __float2half(s1);
            KP.hh[h] = __float2half(s2);
        }
        *(uint4*)(S.qT + d * 8) = QP.u;
        *(uint4*)(S.kT + d * 8) = KP.u;
    }
    __syncthreads();

    // ================= tensor-core phase =================
    const int w = (t >> 5) & 1;       // warp-in-pixel
    const int L = t & 31;
    const int g = L >> 2, tq = L & 3;

    // A fragments: qT rows [32w, 32w+32)
    uint32_t qa[4];
    ldm_x4(qa, smem_u32(S.qT) + (uint32_t)(w * 32 + L) * 16);
    // B fragments: kT rows 0..63 (8 n-tiles)
    uint32_t kb[8];
    ldm_x4(kb + 0, smem_u32(S.kT) + (uint32_t)L * 16);
    ldm_x4(kb + 4, smem_u32(S.kT) + (uint32_t)(32 + L) * 16);

    // Stage-2 mma: 2 M-tiles x 8 N-tiles, K=8
    float Cs[2][8][4];
#pragma unroll
    for (int mi = 0; mi < 2; mi++)
#pragma unroll
        for (int nj = 0; nj < 8; nj++) {
            Cs[mi][nj][0] = Cs[mi][nj][1] = Cs[mi][nj][2] = Cs[mi][nj][3] = 0.f;
            mma_f16_k8(Cs[mi][nj], qa[2 * mi], qa[2 * mi + 1], kb[nj]);
        }

    // exp + Z partials + pack to A-fragments of the output mma
    uint32_t eh[2][8][2];
    float pzlo[8], pzhi[8];
#pragma unroll
    for (int nj = 0; nj < 8; nj++) { pzlo[nj] = 0.f; pzhi[nj] = 0.f; }
#pragma unroll
    for (int mi = 0; mi < 2; mi++)
#pragma unroll
        for (int nj = 0; nj < 8; nj++) {
            float e0 = __expf(Cs[mi][nj][0]);
            float e1 = __expf(Cs[mi][nj][1]);
            float e2 = __expf(Cs[mi][nj][2]);
            float e3 = __expf(Cs[mi][nj][3]);
            pzlo[nj] += e0 + e2;
            pzhi[nj] += e1 + e3;
            eh[mi][nj][0] = pack_h2(e0, e1);
            eh[mi][nj][1] = pack_h2(e2, e3);
        }
    // reduce Z over g (lanes differing in bits 2..4)
#pragma unroll
    for (int nj = 0; nj < 8; nj++) {
#pragma unroll
        for (int m = 4; m <= 16; m <<= 1) {
            pzlo[nj] += __shfl_xor_sync(0xffffffffu, pzlo[nj], m);
            pzhi[nj] += __shfl_xor_sync(0xffffffffu, pzhi[nj], m);
        }
    }
    if (g == 0) {
#pragma unroll
        for (int nj = 0; nj < 8; nj++)
            *(float2*)(S.zpart[w] + nj * 8 + 2 * tq) = make_float2(pzlo[nj], pzhi[nj]);
    }
    __syncthreads();

    // invb[d] = 2 / (zA + zB)   (v+v doubling folded here)
    S.invb[t6] = 2.f / (S.zpart[0][t6] + S.zpart[1][t6]);
    __syncthreads();

    // Output mma: out^T(e,h) = P^T @ vhat, M-tiles 2, N=8, K-tiles 4 (k16)
    float Co[2][4];
    Co[0][0] = Co[0][1] = Co[0][2] = Co[0][3] = 0.f;
    Co[1][0] = Co[1][1] = Co[1][2] = Co[1][3] = 0.f;
#pragma unroll
    for (int kj = 0; kj < 4; kj++) {
        uint32_t bv[2];
        {
            int d0 = 16 * kj + 2 * tq;
            float2 v0 = *(const float2*)(S.v + g * PQ + d0);
            float2 i0 = *(const float2*)(S.invb + d0);
            bv[0] = pack_h2(v0.x * i0.x, v0.y * i0.y);
            float2 v1 = *(const float2*)(S.v + g * PQ + d0 + 8);
            float2 i1 = *(const float2*)(S.invb + d0 + 8);
            bv[1] = pack_h2(v1.x * i1.x, v1.y * i1.y);
        }
#pragma unroll
        for (int mi = 0; mi < 2; mi++) {
            uint32_t av[4] = { eh[mi][2 * kj][0], eh[mi][2 * kj][1],
                               eh[mi][2 * kj + 1][0], eh[mi][2 * kj + 1][1] };
            mma_f16(Co[mi], av, bv);
        }
    }

    // store: scr[b, e*64 + n/64, (n%64)*8 + h], half2 per (e, h-pair)
    {
        const int b = pix >> 12;
        const int n = pix & 4095;
        const size_t base = ((size_t)(b * 4096 + (n >> 6))) * CDIM + (n & 63) * 8 + 2 * tq;
        const size_t estep = (size_t)64 * CDIM;
#pragma unroll
        for (int mi = 0; mi < 2; mi++) {
            int e = w * 32 + mi * 16 + g;
            *(__half2*)(scr + base + (size_t)e * estep) =
                __floats2half2_rn(Co[mi][0], Co[mi][1]);
            *(__half2*)(scr + base + (size_t)(e + 8) * estep) =
                __floats2half2_rn(Co[mi][2], Co[mi][3]);
        }
    }
}

// ---------------------------------------------------------------------------
extern "C" void kernel_launch(void* const* d_in, const int* in_sizes, int n_in,
                              void* d_out, int out_size)
{
    const float* x     = (const float*)d_in[0];
    const float* Wq    = (const float*)d_in[1];
    const float* Wk    = (const float*)d_in[2];
    const float* Wv    = (const float*)d_in[3];
    // d_in[4] = conv_w: dead in the reference
    const float* projw = (const float*)d_in[5];
    const float* projb = (const float*)d_in[6];
    float* out = (float*)d_out;

    cudaFuncSetAttribute(gemm_f16<true>, cudaFuncAttributeMaxDynamicSharedMemorySize, GSMEM);
    cudaFuncSetAttribute(gemm_f16<false>, cudaFuncAttributeMaxDynamicSharedMemorySize, GSMEM);

    __half *x16, *s16, *w16, *qkv16;
    cudaGetSymbolAddress((void**)&x16, g_x16);
    cudaGetSymbolAddress((void**)&s16, g_s16);
    cudaGetSymbolAddress((void**)&w16, g_w16);
    cudaGetSymbolAddress((void**)&qkv16, g_qkv16);

    cvt_x<<<MTOT * CDIM / 4 / 256, 256>>>((const float4*)x, (uint2*)x16, MTOT * CDIM / 4);
    cvt_w<<<dim3(256, 4), 256>>>(
        (const float4*)Wq, (const float4*)Wk, (const float4*)Wv,
        (const float4*)projw, (uint2*)w16);

    // fused QKV GEMM: [16384,512] x [1536,512]^T -> fp16 [16384,1536]
    gemm_f16<true><<<dim3(NQKV / 128, MTOT / 128), 256, GSMEM>>>(
        x16, w16, nullptr, qkv16, NQKV);

    attn_kernel<<<MTOT / 2, 128>>>(qkv16, s16);

    // proj GEMM: [16384,512] x [512,512]^T -> fp32 out
    gemm_f16<false><<<dim3(CDIM / 128, MTOT / 128), 256, GSMEM>>>(
        s16, w16 + 3 * CDIM * CDIM, projb, out, CDIM);
}